// round 12
// baseline (speedup 1.0000x reference)
#include <cuda_runtime.h>
#include <cstdint>

#define NE      1600000
#define NN      100000
#define NF      48
#define EFEAT   16
#define TOT     112
#define HID     128
#define TILE_M  128
#define NTILES  (NE / TILE_M)   // 12500
#define NTH     512

#define SA   132   // activation stride (floats), %32==4 -> conflict-free A frags

// SMEM float offsets (fragment-ordered weight layouts, zero padding)
#define OFF_W1   0                      // 14 k-chunks * 32 lanes * 32 floats = 14336
#define OFF_W2   (OFF_W1 + 14336)      // 16 * 32 * 32 = 16384
#define OFF_W3   (OFF_W2 + 16384)      // 16 * 32 * 12 = 6144
#define OFF_ACT  (OFF_W3 + 6144)       // 128 * 132 = 16896
#define OFF_B1   (OFF_ACT + TILE_M * SA)
#define OFF_B2   (OFF_B1 + HID)
#define OFF_B3   (OFF_B2 + HID)
#define OFF_SRC  (OFF_B3 + NF)
#define OFF_TGT  (OFF_SRC + TILE_M)
#define SMEM_FLOATS (OFF_TGT + TILE_M)
#define SMEM_BYTES  (SMEM_FLOATS * 4)   // 217,280 B

__device__ float g_msum[NN * NF];
__device__ float g_cnt[NN];
__device__ int   g_is64;

__device__ __forceinline__ uint32_t f2tf(float f) {
    uint32_t u;
    asm("cvt.rna.tf32.f32 %0, %1;" : "=r"(u) : "f"(f));
    return u;
}

__device__ __forceinline__ void mma8(float* d, uint32_t a0, uint32_t a1,
                                     uint32_t a2, uint32_t a3,
                                     uint32_t b0, uint32_t b1) {
    asm("mma.sync.aligned.m16n8k8.row.col.f32.tf32.tf32.f32 "
        "{%0,%1,%2,%3}, {%4,%5,%6,%7}, {%8,%9}, {%0,%1,%2,%3};"
        : "+f"(d[0]), "+f"(d[1]), "+f"(d[2]), "+f"(d[3])
        : "r"(a0), "r"(a1), "r"(a2), "r"(a3), "r"(b0), "r"(b1));
}

// vectorized scatter-add: halves atomic lane count vs 2x scalar atomicAdd
__device__ __forceinline__ void red_v2(float* addr, float v0, float v1) {
    asm volatile("red.global.add.v2.f32 [%0], {%1, %2};"
                 :: "l"(addr), "f"(v0), "f"(v1) : "memory");
}

// ---------------- small kernels ----------------
__global__ void detect_kernel(const int* __restrict__ ei) {
    if (threadIdx.x == 0) {
        int nz = 0;
        #pragma unroll 8
        for (int i = 0; i < 64; i++) nz += (ei[2 * i + 1] != 0);
        g_is64 = (nz == 0) ? 1 : 0;
    }
}
__device__ __forceinline__ int load_index(const int* __restrict__ ei, long long pos, int is64) {
    if (is64) return (int)(((const long long*)ei)[pos]);
    return ei[pos];
}
__global__ void count_kernel(const int* __restrict__ ei) {
    int is64 = g_is64;
    long long stride = (long long)gridDim.x * blockDim.x;
    for (long long e = (long long)blockIdx.x * blockDim.x + threadIdx.x; e < NE; e += stride) {
        int t = load_index(ei, (long long)NE + e, is64);
        atomicAdd(&g_cnt[t], 1.0f);
    }
}
// shifts mlp_mma_kernel into ncu's -s 5 -c 1 profile slot
__global__ void noop_kernel() {}

__global__ void finalize_kernel(const float* __restrict__ x, float* __restrict__ out) {
    int i = blockIdx.x * blockDim.x + threadIdx.x;   // float4 index
    if (i < NN * NF / 4) {
        float c = fmaxf(g_cnt[i / 12], 1.0f);
        float4 m = ((const float4*)g_msum)[i];
        float4 xv = ((const float4*)x)[i];
        float4 o;
        o.x = xv.x + m.x / c; o.y = xv.y + m.y / c;
        o.z = xv.z + m.z / c; o.w = xv.w + m.w / c;
        ((float4*)out)[i] = o;
    }
}

// ---------------- main fused kernel ----------------
extern "C" __global__ void __launch_bounds__(NTH, 1)
mlp_mma_kernel(const float* __restrict__ x,
               const int*   __restrict__ ei,
               const float* __restrict__ ef,
               const float* __restrict__ W1, const float* __restrict__ b1,
               const float* __restrict__ W2, const float* __restrict__ b2,
               const float* __restrict__ W3, const float* __restrict__ b3)
{
    extern __shared__ float sm[];
    float* w1f = sm + OFF_W1;
    float* w2f = sm + OFF_W2;
    float* w3f = sm + OFF_W3;
    uint32_t* actb = (uint32_t*)(sm + OFF_ACT);
    float* sb1 = sm + OFF_B1;
    float* sb2 = sm + OFF_B2;
    float* sb3 = sm + OFF_B3;
    int* sSrc = (int*)(sm + OFF_SRC);
    int* sTgt = (int*)(sm + OFF_TGT);
    const float4* bw1 = (const float4*)w1f;
    const float4* bw2 = (const float4*)w2f;
    const float4* bw3 = (const float4*)w3f;

    const int tid  = threadIdx.x;
    const int w    = tid >> 5, lane = tid & 31;
    const int gid  = lane >> 2, tig = lane & 3;
    const int l7   = lane & 7;
    // layers 1-2: M4 x N4 (warp = 32 rows x 32 cols)
    const int wm   = w & 3;          // rows [wm*32, wm*32+32)
    const int wn   = w >> 2;         // cols [wn*32, wn*32+32)
    const int rA   = wm * 32 + gid;
    // layer 3: M8 x N2 (warp = 16 rows x 24 cols)
    const int wm3  = w & 7;
    const int wn3  = w >> 3;
    const int rA3  = wm3 * 16 + gid;

    // ---- load weights once, fragment-ordered + swizzled ----
    for (int i = tid; i < TOT * HID; i += NTH) {
        int kk = i >> 7, n = i & 127;
        int rem = kk & 7, tg = rem & 3, pos = rem >> 2;
        int ln = ((n & 7) << 2) | tg;
        int fidx = (((kk >> 3) * 32 + ln) * 8 + ((n >> 4) ^ (ln & 7))) * 4 + (((n >> 3) & 1) << 1) + pos;
        w1f[fidx] = __uint_as_float(f2tf(W1[i]));
    }
    for (int i = tid; i < HID * HID; i += NTH) {
        int kk = i >> 7, n = i & 127;
        int rem = kk & 7, tg = rem & 3, pos = rem >> 2;
        int ln = ((n & 7) << 2) | tg;
        int fidx = (((kk >> 3) * 32 + ln) * 8 + ((n >> 4) ^ (ln & 7))) * 4 + (((n >> 3) & 1) << 1) + pos;
        w2f[fidx] = __uint_as_float(f2tf(W2[i]));
    }
    for (int i = tid; i < HID * NF; i += NTH) {
        int kk = i / NF, n = i - kk * NF;
        int rem = kk & 7, tg = rem & 3, pos = rem >> 2;
        int ln = ((n & 7) << 2) | tg;
        int fidx = (((kk >> 3) * 32 + ln) * 3 + (n >> 4)) * 4 + (((n >> 3) & 1) << 1) + pos;
        w3f[fidx] = __uint_as_float(f2tf(W3[i]));
    }
    if (tid < HID) { sb1[tid] = b1[tid]; sb2[tid] = b2[tid]; }
    if (tid < NF)  sb3[tid] = b3[tid];
    const int is64 = g_is64;
    __syncthreads();

    for (int T = blockIdx.x; T < NTILES; T += gridDim.x) {
        const long long eBase = (long long)T * TILE_M;
        if (tid < TILE_M) {
            sSrc[tid] = load_index(ei, eBase + tid, is64);
            sTgt[tid] = load_index(ei, (long long)NE + eBase + tid, is64);
        }
        __syncthreads();

        // ---- gather: A[e][0:112] (tf32-rounded) ----
        for (int i = tid; i < TILE_M * 28; i += NTH) {
            int e = i / 28, j = i - e * 28;
            float4 v; int col;
            if (j < 12)      { v = ((const float4*)(x + (size_t)sSrc[e] * NF))[j];       col = j << 2; }
            else if (j < 24) { v = ((const float4*)(x + (size_t)sTgt[e] * NF))[j - 12];  col = 48 + ((j - 12) << 2); }
            else             { v = ((const float4*)(ef + (size_t)(eBase + e) * EFEAT))[j - 24]; col = 96 + ((j - 24) << 2); }
            uint4 t;
            t.x = f2tf(v.x); t.y = f2tf(v.y); t.z = f2tf(v.z); t.w = f2tf(v.w);
            *(uint4*)&actb[e * SA + col] = t;
        }
        __syncthreads();

        // ======== layer 1: H1 = relu(A @ W1 + b1), K=112 ========
        {
            float acc[2][4][4] = {};
            #pragma unroll 2
            for (int k = 0; k < 14; k++) {
                int kc = k * 8 + tig;
                uint32_t a[2][4];
                #pragma unroll
                for (int mt = 0; mt < 2; mt++) {
                    int r = rA + mt * 16;
                    a[mt][0] = actb[r * SA + kc];
                    a[mt][1] = actb[(r + 8) * SA + kc];
                    a[mt][2] = actb[r * SA + kc + 4];
                    a[mt][3] = actb[(r + 8) * SA + kc + 4];
                }
                int bi = (k * 32 + lane) * 8;
                #pragma unroll
                for (int sl = 0; sl < 2; sl++) {
                    float4 q = bw1[bi + ((2 * wn + sl) ^ l7)];
                    #pragma unroll
                    for (int mt = 0; mt < 2; mt++) {
                        mma8(acc[mt][2*sl],   a[mt][0], a[mt][1], a[mt][2], a[mt][3],
                             __float_as_uint(q.x), __float_as_uint(q.y));
                        mma8(acc[mt][2*sl+1], a[mt][0], a[mt][1], a[mt][2], a[mt][3],
                             __float_as_uint(q.z), __float_as_uint(q.w));
                    }
                }
            }
            __syncthreads();   // all MMA reads of A done before overwrite
            #pragma unroll
            for (int mt = 0; mt < 2; mt++) {
                int r0 = rA + mt * 16, r1 = r0 + 8;
                #pragma unroll
                for (int j = 0; j < 4; j++) {
                    int c = wn * 32 + j * 8 + 2 * tig;
                    uint2 u0, u1;
                    u0.x = f2tf(fmaxf(acc[mt][j][0] + sb1[c], 0.f));
                    u0.y = f2tf(fmaxf(acc[mt][j][1] + sb1[c + 1], 0.f));
                    u1.x = f2tf(fmaxf(acc[mt][j][2] + sb1[c], 0.f));
                    u1.y = f2tf(fmaxf(acc[mt][j][3] + sb1[c + 1], 0.f));
                    *(uint2*)&actb[r0 * SA + c] = u0;
                    *(uint2*)&actb[r1 * SA + c] = u1;
                }
            }
        }
        __syncthreads();

        // ======== layer 2: H2 = relu(H1 @ W2 + b2), K=128 ========
        {
            float acc[2][4][4] = {};
            #pragma unroll 2
            for (int k = 0; k < 16; k++) {
                int kc = k * 8 + tig;
                uint32_t a[2][4];
                #pragma unroll
                for (int mt = 0; mt < 2; mt++) {
                    int r = rA + mt * 16;
                    a[mt][0] = actb[r * SA + kc];
                    a[mt][1] = actb[(r + 8) * SA + kc];
                    a[mt][2] = actb[r * SA + kc + 4];
                    a[mt][3] = actb[(r + 8) * SA + kc + 4];
                }
                int bi = (k * 32 + lane) * 8;
                #pragma unroll
                for (int sl = 0; sl < 2; sl++) {
                    float4 q = bw2[bi + ((2 * wn + sl) ^ l7)];
                    #pragma unroll
                    for (int mt = 0; mt < 2; mt++) {
                        mma8(acc[mt][2*sl],   a[mt][0], a[mt][1], a[mt][2], a[mt][3],
                             __float_as_uint(q.x), __float_as_uint(q.y));
                        mma8(acc[mt][2*sl+1], a[mt][0], a[mt][1], a[mt][2], a[mt][3],
                             __float_as_uint(q.z), __float_as_uint(q.w));
                    }
                }
            }
            __syncthreads();
            #pragma unroll
            for (int mt = 0; mt < 2; mt++) {
                int r0 = rA + mt * 16, r1 = r0 + 8;
                #pragma unroll
                for (int j = 0; j < 4; j++) {
                    int c = wn * 32 + j * 8 + 2 * tig;
                    uint2 u0, u1;
                    u0.x = f2tf(fmaxf(acc[mt][j][0] + sb2[c], 0.f));
                    u0.y = f2tf(fmaxf(acc[mt][j][1] + sb2[c + 1], 0.f));
                    u1.x = f2tf(fmaxf(acc[mt][j][2] + sb2[c], 0.f));
                    u1.y = f2tf(fmaxf(acc[mt][j][3] + sb2[c + 1], 0.f));
                    *(uint2*)&actb[r0 * SA + c] = u0;
                    *(uint2*)&actb[r1 * SA + c] = u1;
                }
            }
        }
        __syncthreads();

        // ======== layer 3: msg = H2 @ W3 + b3, N=48 (24 cols/warp, 16 rows/warp) ========
        {
            float acc[3][4] = {};
            #pragma unroll 2
            for (int k = 0; k < 16; k++) {
                int kc = k * 8 + tig;
                uint32_t a0 = actb[rA3 * SA + kc];
                uint32_t a1 = actb[(rA3 + 8) * SA + kc];
                uint32_t a2 = actb[rA3 * SA + kc + 4];
                uint32_t a3 = actb[(rA3 + 8) * SA + kc + 4];
                int bi = (k * 32 + lane) * 3;
                float4 qa = bw3[bi + wn3];
                float4 qb = bw3[bi + wn3 + 1];
                uint32_t b0x = __float_as_uint(wn3 ? qa.z : qa.x);
                uint32_t b0y = __float_as_uint(wn3 ? qa.w : qa.y);
                uint32_t b1x = __float_as_uint(wn3 ? qb.x : qa.z);
                uint32_t b1y = __float_as_uint(wn3 ? qb.y : qa.w);
                uint32_t b2x = __float_as_uint(wn3 ? qb.z : qb.x);
                uint32_t b2y = __float_as_uint(wn3 ? qb.w : qb.y);
                mma8(acc[0], a0, a1, a2, a3, b0x, b0y);
                mma8(acc[1], a0, a1, a2, a3, b1x, b1y);
                mma8(acc[2], a0, a1, a2, a3, b2x, b2y);
            }
            const int t0 = sTgt[rA3], t1 = sTgt[rA3 + 8];
            float* d0 = g_msum + (size_t)t0 * NF;
            float* d1 = g_msum + (size_t)t1 * NF;
            #pragma unroll
            for (int jj = 0; jj < 3; jj++) {
                int c = (wn3 * 3 + jj) * 8 + 2 * tig;   // even -> 8B aligned
                red_v2(d0 + c, acc[jj][0] + sb3[c], acc[jj][1] + sb3[c + 1]);
                red_v2(d1 + c, acc[jj][2] + sb3[c], acc[jj][3] + sb3[c + 1]);
            }
        }
        __syncthreads();   // protect act/sSrc/sTgt before next tile
    }
}

extern "C" void kernel_launch(void* const* d_in, const int* in_sizes, int n_in,
                              void* d_out, int out_size) {
    const float* x  = (const float*)d_in[0];
    const int*   ei = (const int*)d_in[1];
    const float* ef = (const float*)d_in[2];
    const float* W1 = (const float*)d_in[3];
    const float* b1 = (const float*)d_in[4];
    const float* W2 = (const float*)d_in[5];
    const float* b2 = (const float*)d_in[6];
    const float* W3 = (const float*)d_in[7];
    const float* b3 = (const float*)d_in[8];
    float* out = (float*)d_out;

    void* pmsum = nullptr; void* pcnt = nullptr;
    cudaGetSymbolAddress(&pmsum, g_msum);
    cudaGetSymbolAddress(&pcnt, g_cnt);
    cudaMemsetAsync(pmsum, 0, sizeof(float) * NN * NF);
    cudaMemsetAsync(pcnt,  0, sizeof(float) * NN);

    detect_kernel<<<1, 32>>>(ei);
    count_kernel<<<1024, 256>>>(ei);
    noop_kernel<<<1, 1>>>();   // aligns mlp_mma_kernel with ncu's -s 5 -c 1 window

    cudaFuncSetAttribute(mlp_mma_kernel, cudaFuncAttributeMaxDynamicSharedMemorySize, SMEM_BYTES);
    int nsm = 148;
    cudaDeviceGetAttribute(&nsm, cudaDevAttrMultiProcessorCount, 0);
    mlp_mma_kernel<<<nsm, NTH, SMEM_BYTES>>>(x, ei, ef, W1, b1, W2, b2, W3, b3);

    finalize_kernel<<<(NN * NF / 4 + 255) / 256, 256>>>(x, out);
}

// round 13
// speedup vs baseline: 1.0107x; 1.0107x over previous
#include <cuda_runtime.h>
#include <cstdint>

#define NE      1600000
#define NN      100000
#define NF      48
#define EFEAT   16
#define TOT     112
#define HID     128
#define TILE_M  128
#define NTILES  (NE / TILE_M)   // 12500
#define NTH     1024

#define SA   132   // activation stride (floats), %32==4 -> conflict-free A frags

// SMEM float offsets (fragment-ordered weight layouts, zero padding)
#define OFF_W1   0                      // 14 k-chunks * 32 lanes * 32 floats = 14336
#define OFF_W2   (OFF_W1 + 14336)      // 16 * 32 * 32 = 16384
#define OFF_W3   (OFF_W2 + 16384)      // 16 * 32 * 12 = 6144
#define OFF_ACT  (OFF_W3 + 6144)       // 128 * 132 = 16896
#define OFF_B1   (OFF_ACT + TILE_M * SA)
#define OFF_B2   (OFF_B1 + HID)
#define OFF_B3   (OFF_B2 + HID)
#define OFF_SRC  (OFF_B3 + NF)
#define OFF_TGT  (OFF_SRC + TILE_M)
#define SMEM_FLOATS (OFF_TGT + TILE_M)
#define SMEM_BYTES  (SMEM_FLOATS * 4)   // 217,280 B

__device__ float g_msum[NN * NF];
__device__ float g_cnt[NN];
__device__ int   g_is64;

__device__ __forceinline__ uint32_t f2tf(float f) {
    uint32_t u;
    asm("cvt.rna.tf32.f32 %0, %1;" : "=r"(u) : "f"(f));
    return u;
}

__device__ __forceinline__ void mma8(float* d, uint32_t a0, uint32_t a1,
                                     uint32_t a2, uint32_t a3,
                                     uint32_t b0, uint32_t b1) {
    asm("mma.sync.aligned.m16n8k8.row.col.f32.tf32.tf32.f32 "
        "{%0,%1,%2,%3}, {%4,%5,%6,%7}, {%8,%9}, {%0,%1,%2,%3};"
        : "+f"(d[0]), "+f"(d[1]), "+f"(d[2]), "+f"(d[3])
        : "r"(a0), "r"(a1), "r"(a2), "r"(a3), "r"(b0), "r"(b1));
}

// vectorized scatter-add
__device__ __forceinline__ void red_v2(float* addr, float v0, float v1) {
    asm volatile("red.global.add.v2.f32 [%0], {%1, %2};"
                 :: "l"(addr), "f"(v0), "f"(v1) : "memory");
}

// ---------------- small kernels ----------------
__global__ void detect_kernel(const int* __restrict__ ei) {
    if (threadIdx.x == 0) {
        int nz = 0;
        #pragma unroll 8
        for (int i = 0; i < 64; i++) nz += (ei[2 * i + 1] != 0);
        g_is64 = (nz == 0) ? 1 : 0;
    }
}
__device__ __forceinline__ int load_index(const int* __restrict__ ei, long long pos, int is64) {
    if (is64) return (int)(((const long long*)ei)[pos]);
    return ei[pos];
}
__global__ void count_kernel(const int* __restrict__ ei) {
    int is64 = g_is64;
    long long stride = (long long)gridDim.x * blockDim.x;
    for (long long e = (long long)blockIdx.x * blockDim.x + threadIdx.x; e < NE; e += stride) {
        int t = load_index(ei, (long long)NE + e, is64);
        atomicAdd(&g_cnt[t], 1.0f);
    }
}
// shifts mlp_mma_kernel into ncu's -s 5 -c 1 profile slot
__global__ void noop_kernel() {}

__global__ void finalize_kernel(const float* __restrict__ x, float* __restrict__ out) {
    int i = blockIdx.x * blockDim.x + threadIdx.x;   // float4 index
    if (i < NN * NF / 4) {
        float c = fmaxf(g_cnt[i / 12], 1.0f);
        float4 m = ((const float4*)g_msum)[i];
        float4 xv = ((const float4*)x)[i];
        float4 o;
        o.x = xv.x + m.x / c; o.y = xv.y + m.y / c;
        o.z = xv.z + m.z / c; o.w = xv.w + m.w / c;
        ((float4*)out)[i] = o;
    }
}

// ---------------- main fused kernel ----------------
extern "C" __global__ void __launch_bounds__(NTH, 1)
mlp_mma_kernel(const float* __restrict__ x,
               const int*   __restrict__ ei,
               const float* __restrict__ ef,
               const float* __restrict__ W1, const float* __restrict__ b1,
               const float* __restrict__ W2, const float* __restrict__ b2,
               const float* __restrict__ W3, const float* __restrict__ b3)
{
    extern __shared__ float sm[];
    float* w1f = sm + OFF_W1;
    float* w2f = sm + OFF_W2;
    float* w3f = sm + OFF_W3;
    uint32_t* actb = (uint32_t*)(sm + OFF_ACT);
    float* sb1 = sm + OFF_B1;
    float* sb2 = sm + OFF_B2;
    float* sb3 = sm + OFF_B3;
    int* sSrc = (int*)(sm + OFF_SRC);
    int* sTgt = (int*)(sm + OFF_TGT);
    const float4* bw1 = (const float4*)w1f;
    const float4* bw2 = (const float4*)w2f;
    const float4* bw3 = (const float4*)w3f;

    const int tid  = threadIdx.x;
    const int w    = tid >> 5, lane = tid & 31;
    const int gid  = lane >> 2, tig = lane & 3;
    const int l7   = lane & 7;
    // layers 1-2: M4 x N8 (warp = 32 rows x 16 cols)
    const int wm   = w & 3;          // rows [wm*32, wm*32+32)
    const int wn   = w >> 2;         // cols [wn*16, wn*16+16)
    const int rA   = wm * 32 + gid;
    // layer 3: M8 x N3 (24 active warps: 16 rows x 16 cols each)
    const int wm3  = w & 7;
    const int wn3  = w >> 3;         // 0..3; wn3==3 idle in layer 3
    const int rA3  = wm3 * 16 + gid;

    // ---- load weights once, fragment-ordered + swizzled ----
    for (int i = tid; i < TOT * HID; i += NTH) {
        int kk = i >> 7, n = i & 127;
        int rem = kk & 7, tg = rem & 3, pos = rem >> 2;
        int ln = ((n & 7) << 2) | tg;
        int fidx = (((kk >> 3) * 32 + ln) * 8 + ((n >> 4) ^ (ln & 7))) * 4 + (((n >> 3) & 1) << 1) + pos;
        w1f[fidx] = __uint_as_float(f2tf(W1[i]));
    }
    for (int i = tid; i < HID * HID; i += NTH) {
        int kk = i >> 7, n = i & 127;
        int rem = kk & 7, tg = rem & 3, pos = rem >> 2;
        int ln = ((n & 7) << 2) | tg;
        int fidx = (((kk >> 3) * 32 + ln) * 8 + ((n >> 4) ^ (ln & 7))) * 4 + (((n >> 3) & 1) << 1) + pos;
        w2f[fidx] = __uint_as_float(f2tf(W2[i]));
    }
    for (int i = tid; i < HID * NF; i += NTH) {
        int kk = i / NF, n = i - kk * NF;
        int rem = kk & 7, tg = rem & 3, pos = rem >> 2;
        int ln = ((n & 7) << 2) | tg;
        int fidx = (((kk >> 3) * 32 + ln) * 3 + (n >> 4)) * 4 + (((n >> 3) & 1) << 1) + pos;
        w3f[fidx] = __uint_as_float(f2tf(W3[i]));
    }
    if (tid < HID) { sb1[tid] = b1[tid]; sb2[tid] = b2[tid]; }
    if (tid < NF)  sb3[tid] = b3[tid];
    const int is64 = g_is64;
    __syncthreads();

    for (int T = blockIdx.x; T < NTILES; T += gridDim.x) {
        const long long eBase = (long long)T * TILE_M;
        if (tid < TILE_M) {
            sSrc[tid] = load_index(ei, eBase + tid, is64);
            sTgt[tid] = load_index(ei, (long long)NE + eBase + tid, is64);
        }
        __syncthreads();

        // ---- gather: A[e][0:112] (tf32-rounded) ----
        for (int i = tid; i < TILE_M * 28; i += NTH) {
            int e = i / 28, j = i - e * 28;
            float4 v; int col;
            if (j < 12)      { v = ((const float4*)(x + (size_t)sSrc[e] * NF))[j];       col = j << 2; }
            else if (j < 24) { v = ((const float4*)(x + (size_t)sTgt[e] * NF))[j - 12];  col = 48 + ((j - 12) << 2); }
            else             { v = ((const float4*)(ef + (size_t)(eBase + e) * EFEAT))[j - 24]; col = 96 + ((j - 24) << 2); }
            uint4 t;
            t.x = f2tf(v.x); t.y = f2tf(v.y); t.z = f2tf(v.z); t.w = f2tf(v.w);
            *(uint4*)&actb[e * SA + col] = t;
        }
        __syncthreads();

        // ======== layer 1: H1 = relu(A @ W1 + b1), K=112 ========
        {
            float acc[2][2][4] = {};
            #pragma unroll 2
            for (int k = 0; k < 14; k++) {
                int kc = k * 8 + tig;
                uint32_t a[2][4];
                #pragma unroll
                for (int mt = 0; mt < 2; mt++) {
                    int r = rA + mt * 16;
                    a[mt][0] = actb[r * SA + kc];
                    a[mt][1] = actb[(r + 8) * SA + kc];
                    a[mt][2] = actb[r * SA + kc + 4];
                    a[mt][3] = actb[(r + 8) * SA + kc + 4];
                }
                float4 q = bw1[(k * 32 + lane) * 8 + (wn ^ l7)];
                #pragma unroll
                for (int mt = 0; mt < 2; mt++) {
                    mma8(acc[mt][0], a[mt][0], a[mt][1], a[mt][2], a[mt][3],
                         __float_as_uint(q.x), __float_as_uint(q.y));
                    mma8(acc[mt][1], a[mt][0], a[mt][1], a[mt][2], a[mt][3],
                         __float_as_uint(q.z), __float_as_uint(q.w));
                }
            }
            __syncthreads();   // all MMA reads of A done before overwrite
            #pragma unroll
            for (int mt = 0; mt < 2; mt++) {
                int r0 = rA + mt * 16, r1 = r0 + 8;
                #pragma unroll
                for (int j = 0; j < 2; j++) {
                    int c = wn * 16 + j * 8 + 2 * tig;
                    uint2 u0, u1;
                    u0.x = f2tf(fmaxf(acc[mt][j][0] + sb1[c], 0.f));
                    u0.y = f2tf(fmaxf(acc[mt][j][1] + sb1[c + 1], 0.f));
                    u1.x = f2tf(fmaxf(acc[mt][j][2] + sb1[c], 0.f));
                    u1.y = f2tf(fmaxf(acc[mt][j][3] + sb1[c + 1], 0.f));
                    *(uint2*)&actb[r0 * SA + c] = u0;
                    *(uint2*)&actb[r1 * SA + c] = u1;
                }
            }
        }
        __syncthreads();

        // ======== layer 2: H2 = relu(H1 @ W2 + b2), K=128 ========
        {
            float acc[2][2][4] = {};
            #pragma unroll 2
            for (int k = 0; k < 16; k++) {
                int kc = k * 8 + tig;
                uint32_t a[2][4];
                #pragma unroll
                for (int mt = 0; mt < 2; mt++) {
                    int r = rA + mt * 16;
                    a[mt][0] = actb[r * SA + kc];
                    a[mt][1] = actb[(r + 8) * SA + kc];
                    a[mt][2] = actb[r * SA + kc + 4];
                    a[mt][3] = actb[(r + 8) * SA + kc + 4];
                }
                float4 q = bw2[(k * 32 + lane) * 8 + (wn ^ l7)];
                #pragma unroll
                for (int mt = 0; mt < 2; mt++) {
                    mma8(acc[mt][0], a[mt][0], a[mt][1], a[mt][2], a[mt][3],
                         __float_as_uint(q.x), __float_as_uint(q.y));
                    mma8(acc[mt][1], a[mt][0], a[mt][1], a[mt][2], a[mt][3],
                         __float_as_uint(q.z), __float_as_uint(q.w));
                }
            }
            __syncthreads();
            #pragma unroll
            for (int mt = 0; mt < 2; mt++) {
                int r0 = rA + mt * 16, r1 = r0 + 8;
                #pragma unroll
                for (int j = 0; j < 2; j++) {
                    int c = wn * 16 + j * 8 + 2 * tig;
                    uint2 u0, u1;
                    u0.x = f2tf(fmaxf(acc[mt][j][0] + sb2[c], 0.f));
                    u0.y = f2tf(fmaxf(acc[mt][j][1] + sb2[c + 1], 0.f));
                    u1.x = f2tf(fmaxf(acc[mt][j][2] + sb2[c], 0.f));
                    u1.y = f2tf(fmaxf(acc[mt][j][3] + sb2[c + 1], 0.f));
                    *(uint2*)&actb[r0 * SA + c] = u0;
                    *(uint2*)&actb[r1 * SA + c] = u1;
                }
            }
        }
        __syncthreads();

        // ======== layer 3: msg = H2 @ W3 + b3, N=48 (16 cols/warp, 24 warps) ========
        if (wn3 < 3) {
            float acc[2][4] = {};
            #pragma unroll 2
            for (int k = 0; k < 16; k++) {
                int kc = k * 8 + tig;
                uint32_t a0 = actb[rA3 * SA + kc];
                uint32_t a1 = actb[(rA3 + 8) * SA + kc];
                uint32_t a2 = actb[rA3 * SA + kc + 4];
                uint32_t a3 = actb[(rA3 + 8) * SA + kc + 4];
                float4 q = bw3[(k * 32 + lane) * 3 + wn3];
                mma8(acc[0], a0, a1, a2, a3, __float_as_uint(q.x), __float_as_uint(q.y));
                mma8(acc[1], a0, a1, a2, a3, __float_as_uint(q.z), __float_as_uint(q.w));
            }
            const int t0 = sTgt[rA3], t1 = sTgt[rA3 + 8];
            float* d0 = g_msum + (size_t)t0 * NF;
            float* d1 = g_msum + (size_t)t1 * NF;
            #pragma unroll
            for (int jj = 0; jj < 2; jj++) {
                int c = wn3 * 16 + jj * 8 + 2 * tig;   // even -> 8B aligned
                red_v2(d0 + c, acc[jj][0] + sb3[c], acc[jj][1] + sb3[c + 1]);
                red_v2(d1 + c, acc[jj][2] + sb3[c], acc[jj][3] + sb3[c + 1]);
            }
        }
        __syncthreads();   // protect act/sSrc/sTgt before next tile
    }
}

extern "C" void kernel_launch(void* const* d_in, const int* in_sizes, int n_in,
                              void* d_out, int out_size) {
    const float* x  = (const float*)d_in[0];
    const int*   ei = (const int*)d_in[1];
    const float* ef = (const float*)d_in[2];
    const float* W1 = (const float*)d_in[3];
    const float* b1 = (const float*)d_in[4];
    const float* W2 = (const float*)d_in[5];
    const float* b2 = (const float*)d_in[6];
    const float* W3 = (const float*)d_in[7];
    const float* b3 = (const float*)d_in[8];
    float* out = (float*)d_out;

    void* pmsum = nullptr; void* pcnt = nullptr;
    cudaGetSymbolAddress(&pmsum, g_msum);
    cudaGetSymbolAddress(&pcnt, g_cnt);
    cudaMemsetAsync(pmsum, 0, sizeof(float) * NN * NF);
    cudaMemsetAsync(pcnt,  0, sizeof(float) * NN);

    detect_kernel<<<1, 32>>>(ei);
    count_kernel<<<1024, 256>>>(ei);
    noop_kernel<<<1, 1>>>();   // aligns mlp_mma_kernel with ncu's -s 5 -c 1 window

    cudaFuncSetAttribute(mlp_mma_kernel, cudaFuncAttributeMaxDynamicSharedMemorySize, SMEM_BYTES);
    int nsm = 148;
    cudaDeviceGetAttribute(&nsm, cudaDevAttrMultiProcessorCount, 0);
    mlp_mma_kernel<<<nsm, NTH, SMEM_BYTES>>>(x, ei, ef, W1, b1, W2, b2, W3, b3);

    finalize_kernel<<<(NN * NF / 4 + 255) / 256, 256>>>(x, out);
}

// round 14
// speedup vs baseline: 1.1027x; 1.0910x over previous
#include <cuda_runtime.h>
#include <cstdint>

#define NE      1600000
#define NN      100000
#define NF      48
#define EFEAT   16
#define TOT     112
#define HID     128
#define TILE_G  64                      // edges per group-tile
#define NTILES  (NE / TILE_G)           // 25000
#define NTH     1024

#define SA   132   // activation stride (floats), %32==4 -> conflict-free A frags

// SMEM float offsets
#define OFF_W1   0                      // 14*32*32 = 14336
#define OFF_W2   (OFF_W1 + 14336)      // 16*32*32 = 16384
#define OFF_W3   (OFF_W2 + 16384)      // 16*32*12 = 6144
#define OFF_ACT  (OFF_W3 + 6144)       // 2 groups * 64*132 = 16896
#define OFF_B1   (OFF_ACT + 2 * TILE_G * SA)
#define OFF_B2   (OFF_B1 + HID)
#define OFF_B3   (OFF_B2 + HID)
#define OFF_SRC  (OFF_B3 + NF)          // 2*64 ints
#define OFF_TGT  (OFF_SRC + 2 * TILE_G)
#define SMEM_FLOATS (OFF_TGT + 2 * TILE_G)
#define SMEM_BYTES  (SMEM_FLOATS * 4)   // 217,280 B

__device__ float g_msum[NN * NF];
__device__ float g_cnt[NN];
__device__ int   g_is64;

__device__ __forceinline__ uint32_t f2tf(float f) {
    uint32_t u;
    asm("cvt.rna.tf32.f32 %0, %1;" : "=r"(u) : "f"(f));
    return u;
}

__device__ __forceinline__ void mma8(float* d, uint32_t a0, uint32_t a1,
                                     uint32_t a2, uint32_t a3,
                                     uint32_t b0, uint32_t b1) {
    asm("mma.sync.aligned.m16n8k8.row.col.f32.tf32.tf32.f32 "
        "{%0,%1,%2,%3}, {%4,%5,%6,%7}, {%8,%9}, {%0,%1,%2,%3};"
        : "+f"(d[0]), "+f"(d[1]), "+f"(d[2]), "+f"(d[3])
        : "r"(a0), "r"(a1), "r"(a2), "r"(a3), "r"(b0), "r"(b1));
}

__device__ __forceinline__ void red_v2(float* addr, float v0, float v1) {
    asm volatile("red.global.add.v2.f32 [%0], {%1, %2};"
                 :: "l"(addr), "f"(v0), "f"(v1) : "memory");
}

// ---------------- small kernels ----------------
__global__ void detect_kernel(const int* __restrict__ ei) {
    if (threadIdx.x == 0) {
        int nz = 0;
        #pragma unroll 8
        for (int i = 0; i < 64; i++) nz += (ei[2 * i + 1] != 0);
        g_is64 = (nz == 0) ? 1 : 0;
    }
}
__device__ __forceinline__ int load_index(const int* __restrict__ ei, long long pos, int is64) {
    if (is64) return (int)(((const long long*)ei)[pos]);
    return ei[pos];
}
__global__ void count_kernel(const int* __restrict__ ei) {
    int is64 = g_is64;
    long long stride = (long long)gridDim.x * blockDim.x;
    for (long long e = (long long)blockIdx.x * blockDim.x + threadIdx.x; e < NE; e += stride) {
        int t = load_index(ei, (long long)NE + e, is64);
        atomicAdd(&g_cnt[t], 1.0f);
    }
}
__global__ void noop_kernel() {}

__global__ void finalize_kernel(const float* __restrict__ x, float* __restrict__ out) {
    int i = blockIdx.x * blockDim.x + threadIdx.x;   // float4 index
    if (i < NN * NF / 4) {
        float c = fmaxf(g_cnt[i / 12], 1.0f);
        float4 m = ((const float4*)g_msum)[i];
        float4 xv = ((const float4*)x)[i];
        float4 o;
        o.x = xv.x + m.x / c; o.y = xv.y + m.y / c;
        o.z = xv.z + m.z / c; o.w = xv.w + m.w / c;
        ((float4*)out)[i] = o;
    }
}

// ---------------- main fused kernel: 2 independent 16-warp pipelines ----------------
extern "C" __global__ void __launch_bounds__(NTH, 1)
mlp_mma_kernel(const float* __restrict__ x,
               const int*   __restrict__ ei,
               const float* __restrict__ ef,
               const float* __restrict__ W1, const float* __restrict__ b1,
               const float* __restrict__ W2, const float* __restrict__ b2,
               const float* __restrict__ W3, const float* __restrict__ b3)
{
    extern __shared__ float sm[];
    float* w1f = sm + OFF_W1;
    float* w2f = sm + OFF_W2;
    float* w3f = sm + OFF_W3;
    float* sb1 = sm + OFF_B1;
    float* sb2 = sm + OFF_B2;
    float* sb3 = sm + OFF_B3;
    const float4* bw1 = (const float4*)w1f;
    const float4* bw2 = (const float4*)w2f;
    const float4* bw3 = (const float4*)w3f;

    const int tid  = threadIdx.x;
    const int w    = tid >> 5, lane = tid & 31;
    const int gid  = lane >> 2, tig = lane & 3;
    const int l7   = lane & 7;
    const int g    = w >> 4;         // pipeline group 0/1
    const int wl   = w & 15;         // warp within group
    const int gtid = tid & 511;      // thread within group
    // group partition (64 edges): M4 x N4 (warp = 16 rows x 32 cols)
    const int wm   = wl & 3;         // rows [wm*16, wm*16+16)
    const int wn   = wl >> 2;        // cols [wn*32, +32); layer3: cols [wn*16,+16), wn==3 idle
    const int rA   = wm * 16 + gid;

    uint32_t* actg = (uint32_t*)(sm + OFF_ACT) + g * TILE_G * SA;
    int* sSrcg = (int*)(sm + OFF_SRC) + g * TILE_G;
    int* sTgtg = (int*)(sm + OFF_TGT) + g * TILE_G;

    // named barrier per group (ids 1 and 2), 512 threads each
    #define GBAR() asm volatile("bar.sync %0, 512;" :: "r"(g + 1) : "memory")

    // ---- load weights once, fragment-ordered + swizzled (all 1024 threads) ----
    for (int i = tid; i < TOT * HID; i += NTH) {
        int kk = i >> 7, n = i & 127;
        int rem = kk & 7, tg = rem & 3, pos = rem >> 2;
        int ln = ((n & 7) << 2) | tg;
        int fidx = (((kk >> 3) * 32 + ln) * 8 + ((n >> 4) ^ (ln & 7))) * 4 + (((n >> 3) & 1) << 1) + pos;
        w1f[fidx] = __uint_as_float(f2tf(W1[i]));
    }
    for (int i = tid; i < HID * HID; i += NTH) {
        int kk = i >> 7, n = i & 127;
        int rem = kk & 7, tg = rem & 3, pos = rem >> 2;
        int ln = ((n & 7) << 2) | tg;
        int fidx = (((kk >> 3) * 32 + ln) * 8 + ((n >> 4) ^ (ln & 7))) * 4 + (((n >> 3) & 1) << 1) + pos;
        w2f[fidx] = __uint_as_float(f2tf(W2[i]));
    }
    for (int i = tid; i < HID * NF; i += NTH) {
        int kk = i / NF, n = i - kk * NF;
        int rem = kk & 7, tg = rem & 3, pos = rem >> 2;
        int ln = ((n & 7) << 2) | tg;
        int fidx = (((kk >> 3) * 32 + ln) * 3 + (n >> 4)) * 4 + (((n >> 3) & 1) << 1) + pos;
        w3f[fidx] = __uint_as_float(f2tf(W3[i]));
    }
    if (tid < HID) { sb1[tid] = b1[tid]; sb2[tid] = b2[tid]; }
    if (tid < NF)  sb3[tid] = b3[tid];
    const int is64 = g_is64;
    __syncthreads();

    for (int T = blockIdx.x * 2 + g; T < NTILES; T += gridDim.x * 2) {
        const long long eBase = (long long)T * TILE_G;
        if (gtid < TILE_G) {
            sSrcg[gtid] = load_index(ei, eBase + gtid, is64);
            sTgtg[gtid] = load_index(ei, (long long)NE + eBase + gtid, is64);
        }
        GBAR();

        // ---- gather: A[e][0:112] (tf32-rounded), 64 edges ----
        for (int i = gtid; i < TILE_G * 28; i += 512) {
            int e = i / 28, j = i - e * 28;
            float4 v; int col;
            if (j < 12)      { v = ((const float4*)(x + (size_t)sSrcg[e] * NF))[j];      col = j << 2; }
            else if (j < 24) { v = ((const float4*)(x + (size_t)sTgtg[e] * NF))[j - 12]; col = 48 + ((j - 12) << 2); }
            else             { v = ((const float4*)(ef + (size_t)(eBase + e) * EFEAT))[j - 24]; col = 96 + ((j - 24) << 2); }
            uint4 t;
            t.x = f2tf(v.x); t.y = f2tf(v.y); t.z = f2tf(v.z); t.w = f2tf(v.w);
            *(uint4*)&actg[e * SA + col] = t;
        }
        GBAR();

        // ======== layer 1: H1 = relu(A @ W1 + b1), K=112 ========
        {
            float acc[4][4] = {};
            #pragma unroll 2
            for (int k = 0; k < 14; k++) {
                int kc = k * 8 + tig;
                uint32_t a0 = actg[rA * SA + kc];
                uint32_t a1 = actg[(rA + 8) * SA + kc];
                uint32_t a2 = actg[rA * SA + kc + 4];
                uint32_t a3 = actg[(rA + 8) * SA + kc + 4];
                int bi = (k * 32 + lane) * 8;
                #pragma unroll
                for (int sl = 0; sl < 2; sl++) {
                    float4 q = bw1[bi + ((2 * wn + sl) ^ l7)];
                    mma8(acc[2*sl],   a0, a1, a2, a3, __float_as_uint(q.x), __float_as_uint(q.y));
                    mma8(acc[2*sl+1], a0, a1, a2, a3, __float_as_uint(q.z), __float_as_uint(q.w));
                }
            }
            GBAR();   // group MMA reads done before overwrite
            #pragma unroll
            for (int j = 0; j < 4; j++) {
                int c = wn * 32 + j * 8 + 2 * tig;
                uint2 u0, u1;
                u0.x = f2tf(fmaxf(acc[j][0] + sb1[c], 0.f));
                u0.y = f2tf(fmaxf(acc[j][1] + sb1[c + 1], 0.f));
                u1.x = f2tf(fmaxf(acc[j][2] + sb1[c], 0.f));
                u1.y = f2tf(fmaxf(acc[j][3] + sb1[c + 1], 0.f));
                *(uint2*)&actg[rA * SA + c] = u0;
                *(uint2*)&actg[(rA + 8) * SA + c] = u1;
            }
        }
        GBAR();

        // ======== layer 2: H2 = relu(H1 @ W2 + b2), K=128 ========
        {
            float acc[4][4] = {};
            #pragma unroll 2
            for (int k = 0; k < 16; k++) {
                int kc = k * 8 + tig;
                uint32_t a0 = actg[rA * SA + kc];
                uint32_t a1 = actg[(rA + 8) * SA + kc];
                uint32_t a2 = actg[rA * SA + kc + 4];
                uint32_t a3 = actg[(rA + 8) * SA + kc + 4];
                int bi = (k * 32 + lane) * 8;
                #pragma unroll
                for (int sl = 0; sl < 2; sl++) {
                    float4 q = bw2[bi + ((2 * wn + sl) ^ l7)];
                    mma8(acc[2*sl],   a0, a1, a2, a3, __float_as_uint(q.x), __float_as_uint(q.y));
                    mma8(acc[2*sl+1], a0, a1, a2, a3, __float_as_uint(q.z), __float_as_uint(q.w));
                }
            }
            GBAR();
            #pragma unroll
            for (int j = 0; j < 4; j++) {
                int c = wn * 32 + j * 8 + 2 * tig;
                uint2 u0, u1;
                u0.x = f2tf(fmaxf(acc[j][0] + sb2[c], 0.f));
                u0.y = f2tf(fmaxf(acc[j][1] + sb2[c + 1], 0.f));
                u1.x = f2tf(fmaxf(acc[j][2] + sb2[c], 0.f));
                u1.y = f2tf(fmaxf(acc[j][3] + sb2[c + 1], 0.f));
                *(uint2*)&actg[rA * SA + c] = u0;
                *(uint2*)&actg[(rA + 8) * SA + c] = u1;
            }
        }
        GBAR();

        // ======== layer 3: msg = H2 @ W3 + b3, N=48 (16 cols/warp, 12 warps) ========
        if (wn < 3) {
            float acc[2][4] = {};
            #pragma unroll 2
            for (int k = 0; k < 16; k++) {
                int kc = k * 8 + tig;
                uint32_t a0 = actg[rA * SA + kc];
                uint32_t a1 = actg[(rA + 8) * SA + kc];
                uint32_t a2 = actg[rA * SA + kc + 4];
                uint32_t a3 = actg[(rA + 8) * SA + kc + 4];
                float4 q = bw3[(k * 32 + lane) * 3 + wn];
                mma8(acc[0], a0, a1, a2, a3, __float_as_uint(q.x), __float_as_uint(q.y));
                mma8(acc[1], a0, a1, a2, a3, __float_as_uint(q.z), __float_as_uint(q.w));
            }
            const int t0 = sTgtg[rA], t1 = sTgtg[rA + 8];
            float* d0 = g_msum + (size_t)t0 * NF;
            float* d1 = g_msum + (size_t)t1 * NF;
            #pragma unroll
            for (int jj = 0; jj < 2; jj++) {
                int c = wn * 16 + jj * 8 + 2 * tig;   // even -> 8B aligned
                red_v2(d0 + c, acc[jj][0] + sb3[c], acc[jj][1] + sb3[c + 1]);
                red_v2(d1 + c, acc[jj][2] + sb3[c], acc[jj][3] + sb3[c + 1]);
            }
        }
        GBAR();   // protect act/sSrc/sTgt before next tile
    }
    #undef GBAR
}

extern "C" void kernel_launch(void* const* d_in, const int* in_sizes, int n_in,
                              void* d_out, int out_size) {
    const float* x  = (const float*)d_in[0];
    const int*   ei = (const int*)d_in[1];
    const float* ef = (const float*)d_in[2];
    const float* W1 = (const float*)d_in[3];
    const float* b1 = (const float*)d_in[4];
    const float* W2 = (const float*)d_in[5];
    const float* b2 = (const float*)d_in[6];
    const float* W3 = (const float*)d_in[7];
    const float* b3 = (const float*)d_in[8];
    float* out = (float*)d_out;

    void* pmsum = nullptr; void* pcnt = nullptr;
    cudaGetSymbolAddress(&pmsum, g_msum);
    cudaGetSymbolAddress(&pcnt, g_cnt);
    cudaMemsetAsync(pmsum, 0, sizeof(float) * NN * NF);
    cudaMemsetAsync(pcnt,  0, sizeof(float) * NN);

    detect_kernel<<<1, 32>>>(ei);
    count_kernel<<<1024, 256>>>(ei);
    noop_kernel<<<1, 1>>>();   // aligns mlp_mma_kernel with ncu's -s 5 -c 1 window

    cudaFuncSetAttribute(mlp_mma_kernel, cudaFuncAttributeMaxDynamicSharedMemorySize, SMEM_BYTES);
    int nsm = 148;
    cudaDeviceGetAttribute(&nsm, cudaDevAttrMultiProcessorCount, 0);
    mlp_mma_kernel<<<nsm, NTH, SMEM_BYTES>>>(x, ei, ef, W1, b1, W2, b2, W3, b3);

    finalize_kernel<<<(NN * NF / 4 + 255) / 256, 256>>>(x, out);
}

// round 16
// speedup vs baseline: 1.1470x; 1.0402x over previous
#include <cuda_runtime.h>
#include <cstdint>

#define NE      1600000
#define NN      100000
#define NF      48
#define EFEAT   16
#define TOT     112
#define HID     128
#define TILE_G  64                      // edges per group-tile
#define NTILES  (NE / TILE_G)           // 25000
#define NTH     512

#define SA   132   // activation stride (floats), %32==4 -> conflict-free A frags

// SMEM float offsets (fragment-ordered tf32 weights + XOR swizzle)
#define OFF_W1   0                      // 14*32*32 = 14336
#define OFF_W2   (OFF_W1 + 14336)      // 16*32*32 = 16384
#define OFF_W3   (OFF_W2 + 16384)      // 16*32*12 = 6144
#define OFF_ACT  (OFF_W3 + 6144)       // 2 groups * 64*132 = 16896
#define OFF_B1   (OFF_ACT + 2 * TILE_G * SA)
#define OFF_B2   (OFF_B1 + HID)
#define OFF_B3   (OFF_B2 + HID)
#define OFF_SRC  (OFF_B3 + NF)
#define OFF_TGT  (OFF_SRC + 2 * TILE_G)
#define SMEM_FLOATS (OFF_TGT + 2 * TILE_G)
#define SMEM_BYTES  (SMEM_FLOATS * 4)   // 217,280 B

__device__ float g_msum[NN * NF];
__device__ float g_cnt[NN];
__device__ int   g_is64;

__device__ __forceinline__ uint32_t f2tf(float f) {
    uint32_t u;
    asm("cvt.rna.tf32.f32 %0, %1;" : "=r"(u) : "f"(f));
    return u;
}

__device__ __forceinline__ void mma8(float* d, uint32_t a0, uint32_t a1,
                                     uint32_t a2, uint32_t a3,
                                     uint32_t b0, uint32_t b1) {
    asm("mma.sync.aligned.m16n8k8.row.col.f32.tf32.tf32.f32 "
        "{%0,%1,%2,%3}, {%4,%5,%6,%7}, {%8,%9}, {%0,%1,%2,%3};"
        : "+f"(d[0]), "+f"(d[1]), "+f"(d[2]), "+f"(d[3])
        : "r"(a0), "r"(a1), "r"(a2), "r"(a3), "r"(b0), "r"(b1));
}

__device__ __forceinline__ void red_v2(float* addr, float v0, float v1) {
    asm volatile("red.global.add.v2.f32 [%0], {%1, %2};"
                 :: "l"(addr), "f"(v0), "f"(v1) : "memory");
}

// ---------------- small kernels ----------------
__global__ void detect_kernel(const int* __restrict__ ei) {
    if (threadIdx.x == 0) {
        int nz = 0;
        #pragma unroll 8
        for (int i = 0; i < 64; i++) nz += (ei[2 * i + 1] != 0);
        g_is64 = (nz == 0) ? 1 : 0;
    }
}
__device__ __forceinline__ int load_index(const int* __restrict__ ei, long long pos, int is64) {
    if (is64) return (int)(((const long long*)ei)[pos]);
    return ei[pos];
}
__global__ void count_kernel(const int* __restrict__ ei) {
    int is64 = g_is64;
    long long stride = (long long)gridDim.x * blockDim.x;
    for (long long e = (long long)blockIdx.x * blockDim.x + threadIdx.x; e < NE; e += stride) {
        int t = load_index(ei, (long long)NE + e, is64);
        atomicAdd(&g_cnt[t], 1.0f);
    }
}
__global__ void noop_kernel() {}

__global__ void finalize_kernel(const float* __restrict__ x, float* __restrict__ out) {
    int i = blockIdx.x * blockDim.x + threadIdx.x;   // float4 index
    if (i < NN * NF / 4) {
        float c = fmaxf(g_cnt[i / 12], 1.0f);
        float4 m = ((const float4*)g_msum)[i];
        float4 xv = ((const float4*)x)[i];
        float4 o;
        o.x = xv.x + m.x / c; o.y = xv.y + m.y / c;
        o.z = xv.z + m.z / c; o.w = xv.w + m.w / c;
        ((float4*)out)[i] = o;
    }
}

// ---------------- main fused kernel: 2 pipelines x 8 warps, 32x32 warp tiles ----------------
extern "C" __global__ void __launch_bounds__(NTH, 1)
mlp_mma_kernel(const float* __restrict__ x,
               const int*   __restrict__ ei,
               const float* __restrict__ ef,
               const float* __restrict__ W1, const float* __restrict__ b1,
               const float* __restrict__ W2, const float* __restrict__ b2,
               const float* __restrict__ W3, const float* __restrict__ b3)
{
    extern __shared__ float sm[];
    float* w1f = sm + OFF_W1;
    float* w2f = sm + OFF_W2;
    float* w3f = sm + OFF_W3;
    float* sb1 = sm + OFF_B1;
    float* sb2 = sm + OFF_B2;
    float* sb3 = sm + OFF_B3;
    const float4* bw1 = (const float4*)w1f;
    const float4* bw2 = (const float4*)w2f;
    const float4* bw3 = (const float4*)w3f;

    const int tid  = threadIdx.x;
    const int w    = tid >> 5, lane = tid & 31;
    const int gid  = lane >> 2, tig = lane & 3;
    const int l7   = lane & 7;
    const int g    = w >> 3;         // pipeline group 0/1
    const int wl   = w & 7;          // warp within group
    const int gtid = tid & 255;      // thread within group
    // layers 1-2: M2 x N4 (warp = 32 rows x 32 cols)
    const int wm   = wl & 1;         // rows [wm*32, +32)
    const int wn   = wl >> 1;        // cols [wn*32, +32)
    const int rA   = wm * 32 + gid;  // m-tiles at rA, rA+16 (rows +8 within)
    // layer 3: M2 x N3 (6 warps, 32 rows x 16 cols; wl 6,7 idle)
    const int wm3  = wl & 1;
    const int wn3  = wl >> 1;        // 0..2 active
    const int rA3  = wm3 * 32 + gid;

    uint32_t* actg = (uint32_t*)(sm + OFF_ACT) + g * TILE_G * SA;
    int* sSrcg = (int*)(sm + OFF_SRC) + g * TILE_G;
    int* sTgtg = (int*)(sm + OFF_TGT) + g * TILE_G;

    #define GBAR() asm volatile("bar.sync %0, 256;" :: "r"(g + 1) : "memory")

    // ---- load weights once, fragment-ordered + swizzled (all 512 threads) ----
    for (int i = tid; i < TOT * HID; i += NTH) {
        int kk = i >> 7, n = i & 127;
        int rem = kk & 7, tg = rem & 3, pos = rem >> 2;
        int ln = ((n & 7) << 2) | tg;
        int fidx = (((kk >> 3) * 32 + ln) * 8 + ((n >> 4) ^ (ln & 7))) * 4 + (((n >> 3) & 1) << 1) + pos;
        w1f[fidx] = __uint_as_float(f2tf(W1[i]));
    }
    for (int i = tid; i < HID * HID; i += NTH) {
        int kk = i >> 7, n = i & 127;
        int rem = kk & 7, tg = rem & 3, pos = rem >> 2;
        int ln = ((n & 7) << 2) | tg;
        int fidx = (((kk >> 3) * 32 + ln) * 8 + ((n >> 4) ^ (ln & 7))) * 4 + (((n >> 3) & 1) << 1) + pos;
        w2f[fidx] = __uint_as_float(f2tf(W2[i]));
    }
    for (int i = tid; i < HID * NF; i += NTH) {
        int kk = i / NF, n = i - kk * NF;
        int rem = kk & 7, tg = rem & 3, pos = rem >> 2;
        int ln = ((n & 7) << 2) | tg;
        int fidx = (((kk >> 3) * 32 + ln) * 3 + (n >> 4)) * 4 + (((n >> 3) & 1) << 1) + pos;
        w3f[fidx] = __uint_as_float(f2tf(W3[i]));
    }
    if (tid < HID) { sb1[tid] = b1[tid]; sb2[tid] = b2[tid]; }
    if (tid < NF)  sb3[tid] = b3[tid];
    const int is64 = g_is64;
    __syncthreads();

    for (int T = blockIdx.x * 2 + g; T < NTILES; T += gridDim.x * 2) {
        const long long eBase = (long long)T * TILE_G;
        if (gtid < TILE_G) {
            sSrcg[gtid] = load_index(ei, eBase + gtid, is64);
            sTgtg[gtid] = load_index(ei, (long long)NE + eBase + gtid, is64);
        }
        GBAR();

        // ---- gather: A[e][0:112] (tf32-rounded), 64 edges, 256 threads ----
        for (int i = gtid; i < TILE_G * 28; i += 256) {
            int e = i / 28, j = i - e * 28;
            float4 v; int col;
            if (j < 12)      { v = ((const float4*)(x + (size_t)sSrcg[e] * NF))[j];      col = j << 2; }
            else if (j < 24) { v = ((const float4*)(x + (size_t)sTgtg[e] * NF))[j - 12]; col = 48 + ((j - 12) << 2); }
            else             { v = ((const float4*)(ef + (size_t)(eBase + e) * EFEAT))[j - 24]; col = 96 + ((j - 24) << 2); }
            uint4 t;
            t.x = f2tf(v.x); t.y = f2tf(v.y); t.z = f2tf(v.z); t.w = f2tf(v.w);
            *(uint4*)&actg[e * SA + col] = t;
        }
        GBAR();

        // ======== layer 1: H1 = relu(A @ W1 + b1), K=112 ========
        {
            float acc[2][4][4] = {};
            #pragma unroll 2
            for (int k = 0; k < 14; k++) {
                int kc = k * 8 + tig;
                uint32_t a[2][4];
                #pragma unroll
                for (int mt = 0; mt < 2; mt++) {
                    int r = rA + mt * 16;
                    a[mt][0] = actg[r * SA + kc];
                    a[mt][1] = actg[(r + 8) * SA + kc];
                    a[mt][2] = actg[r * SA + kc + 4];
                    a[mt][3] = actg[(r + 8) * SA + kc + 4];
                }
                int bi = (k * 32 + lane) * 8;
                #pragma unroll
                for (int sl = 0; sl < 2; sl++) {
                    float4 q = bw1[bi + ((2 * wn + sl) ^ l7)];
                    #pragma unroll
                    for (int mt = 0; mt < 2; mt++) {
                        mma8(acc[mt][2*sl],   a[mt][0], a[mt][1], a[mt][2], a[mt][3],
                             __float_as_uint(q.x), __float_as_uint(q.y));
                        mma8(acc[mt][2*sl+1], a[mt][0], a[mt][1], a[mt][2], a[mt][3],
                             __float_as_uint(q.z), __float_as_uint(q.w));
                    }
                }
            }
            GBAR();   // group MMA reads done before overwrite
            #pragma unroll
            for (int mt = 0; mt < 2; mt++) {
                int r0 = rA + mt * 16, r1 = r0 + 8;
                #pragma unroll
                for (int j = 0; j < 4; j++) {
                    int c = wn * 32 + j * 8 + 2 * tig;
                    uint2 u0, u1;
                    u0.x = f2tf(fmaxf(acc[mt][j][0] + sb1[c], 0.f));
                    u0.y = f2tf(fmaxf(acc[mt][j][1] + sb1[c + 1], 0.f));
                    u1.x = f2tf(fmaxf(acc[mt][j][2] + sb1[c], 0.f));
                    u1.y = f2tf(fmaxf(acc[mt][j][3] + sb1[c + 1], 0.f));
                    *(uint2*)&actg[r0 * SA + c] = u0;
                    *(uint2*)&actg[r1 * SA + c] = u1;
                }
            }
        }
        GBAR();

        // ======== layer 2: H2 = relu(H1 @ W2 + b2), K=128 ========
        {
            float acc[2][4][4] = {};
            #pragma unroll 2
            for (int k = 0; k < 16; k++) {
                int kc = k * 8 + tig;
                uint32_t a[2][4];
                #pragma unroll
                for (int mt = 0; mt < 2; mt++) {
                    int r = rA + mt * 16;
                    a[mt][0] = actg[r * SA + kc];
                    a[mt][1] = actg[(r + 8) * SA + kc];
                    a[mt][2] = actg[r * SA + kc + 4];
                    a[mt][3] = actg[(r + 8) * SA + kc + 4];
                }
                int bi = (k * 32 + lane) * 8;
                #pragma unroll
                for (int sl = 0; sl < 2; sl++) {
                    float4 q = bw2[bi + ((2 * wn + sl) ^ l7)];
                    #pragma unroll
                    for (int mt = 0; mt < 2; mt++) {
                        mma8(acc[mt][2*sl],   a[mt][0], a[mt][1], a[mt][2], a[mt][3],
                             __float_as_uint(q.x), __float_as_uint(q.y));
                        mma8(acc[mt][2*sl+1], a[mt][0], a[mt][1], a[mt][2], a[mt][3],
                             __float_as_uint(q.z), __float_as_uint(q.w));
                    }
                }
            }
            GBAR();
            #pragma unroll
            for (int mt = 0; mt < 2; mt++) {
                int r0 = rA + mt * 16, r1 = r0 + 8;
                #pragma unroll
                for (int j = 0; j < 4; j++) {
                    int c = wn * 32 + j * 8 + 2 * tig;
                    uint2 u0, u1;
                    u0.x = f2tf(fmaxf(acc[mt][j][0] + sb2[c], 0.f));
                    u0.y = f2tf(fmaxf(acc[mt][j][1] + sb2[c + 1], 0.f));
                    u1.x = f2tf(fmaxf(acc[mt][j][2] + sb2[c], 0.f));
                    u1.y = f2tf(fmaxf(acc[mt][j][3] + sb2[c + 1], 0.f));
                    *(uint2*)&actg[r0 * SA + c] = u0;
                    *(uint2*)&actg[r1 * SA + c] = u1;
                }
            }
        }
        GBAR();

        // ======== layer 3: msg = H2 @ W3 + b3, N=48 (16 cols/warp, 6 warps) ========
        if (wn3 < 3) {
            float acc[2][2][4] = {};
            #pragma unroll 2
            for (int k = 0; k < 16; k++) {
                int kc = k * 8 + tig;
                uint32_t a[2][4];
                #pragma unroll
                for (int mt = 0; mt < 2; mt++) {
                    int r = rA3 + mt * 16;
                    a[mt][0] = actg[r * SA + kc];
                    a[mt][1] = actg[(r + 8) * SA + kc];
                    a[mt][2] = actg[r * SA + kc + 4];
                    a[mt][3] = actg[(r + 8) * SA + kc + 4];
                }
                float4 q = bw3[(k * 32 + lane) * 3 + wn3];
                #pragma unroll
                for (int mt = 0; mt < 2; mt++) {
                    mma8(acc[mt][0], a[mt][0], a[mt][1], a[mt][2], a[mt][3],
                         __float_as_uint(q.x), __float_as_uint(q.y));
                    mma8(acc[mt][1], a[mt][0], a[mt][1], a[mt][2], a[mt][3],
                         __float_as_uint(q.z), __float_as_uint(q.w));
                }
            }
            #pragma unroll
            for (int mt = 0; mt < 2; mt++) {
                int r0 = rA3 + mt * 16, r1 = r0 + 8;
                const int t0 = sTgtg[r0], t1 = sTgtg[r1];
                float* d0 = g_msum + (size_t)t0 * NF;
                float* d1 = g_msum + (size_t)t1 * NF;
                #pragma unroll
                for (int jj = 0; jj < 2; jj++) {
                    int c = wn3 * 16 + jj * 8 + 2 * tig;   // even -> 8B aligned
                    red_v2(d0 + c, acc[mt][jj][0] + sb3[c], acc[mt][jj][1] + sb3[c + 1]);
                    red_v2(d1 + c, acc[mt][jj][2] + sb3[c], acc[mt][jj][3] + sb3[c + 1]);
                }
            }
        }
        GBAR();   // protect act/sSrc/sTgt before next tile
    }
    #undef GBAR
}

extern "C" void kernel_launch(void* const* d_in, const int* in_sizes, int n_in,
                              void* d_out, int out_size) {
    const float* x  = (const float*)d_in[0];
    const int*   ei = (const int*)d_in[1];
    const float* ef = (const float*)d_in[2];
    const float* W1 = (const float*)d_in[3];
    const float* b1 = (const float*)d_in[4];
    const float* W2 = (const float*)d_in[5];
    const float* b2 = (const float*)d_in[6];
    const float* W3 = (const float*)d_in[7];
    const float* b3 = (const float*)d_in[8];
    float* out = (float*)d_out;

    void* pmsum = nullptr; void* pcnt = nullptr;
    cudaGetSymbolAddress(&pmsum, g_msum);
    cudaGetSymbolAddress(&pcnt, g_cnt);
    cudaMemsetAsync(pmsum, 0, sizeof(float) * NN * NF);
    cudaMemsetAsync(pcnt,  0, sizeof(float) * NN);

    detect_kernel<<<1, 32>>>(ei);
    count_kernel<<<1024, 256>>>(ei);
    noop_kernel<<<1, 1>>>();   // aligns mlp_mma_kernel with ncu's -s 5 -c 1 window

    cudaFuncSetAttribute(mlp_mma_kernel, cudaFuncAttributeMaxDynamicSharedMemorySize, SMEM_BYTES);
    int nsm = 148;
    cudaDeviceGetAttribute(&nsm, cudaDevAttrMultiProcessorCount, 0);
    mlp_mma_kernel<<<nsm, NTH, SMEM_BYTES>>>(x, ei, ef, W1, b1, W2, b2, W3, b3);

    finalize_kernel<<<(NN * NF / 4 + 255) / 256, 256>>>(x, out);
}